// round 5
// baseline (speedup 1.0000x reference)
#include <cuda_runtime.h>
#include <math.h>

// Fixed dataset shapes
#define NN 100000
#define EMAX 1600000
#define NDIM 64
#define NB_SCAN 25   // ceil(NN/4096)

typedef unsigned long long ull;

// ---------------- scratch ----------------
__device__ float g_AB[NN * 256];      // per-node [A+b1 (128) | B (128)]
__device__ float g_Hagg[NN * 128];    // per-dst sum of relu(hidden)
__device__ float g_degf[NN];          // in-degree (float)
// CSR build
__device__ int   g_cnt[NN];
__device__ int   g_off[NN + 1];
__device__ int   g_cur[NN];
__device__ int   g_bsum[NB_SCAN];
__device__ int   g_bexcl[NB_SCAN];
__device__ int2  g_epack[EMAX];       // (src, bitcast attr)
// repacked weights (k-pair interleaved for f32x2: [(k>>1)*NT + c]*2 + (k&1))
__device__ float g_Wpre[64 * 256];
__device__ float g_b1ext[256];
__device__ float g_w1e[128];
__device__ float g_Whht[64 * 192];    // Whh^T interleaved
__device__ float g_Wc[128 * 192];     // (W2^T @ Wih^T) interleaved
__device__ float g_bc[192];           // b2 @ Wih^T

// ---------------- f32x2 helpers ----------------
__device__ __forceinline__ void ffma2(ull& d, ull a, ull b) {
    asm("fma.rn.f32x2 %0, %1, %2, %0;" : "+l"(d) : "l"(a), "l"(b));
}
__device__ __forceinline__ float unpack_sum(ull v) {
    float lo, hi;
    asm("mov.b64 {%0, %1}, %2;" : "=f"(lo), "=f"(hi) : "l"(v));
    return lo + hi;
}

// ---------------- weight repack ----------------
__global__ void prep_kernel(const float* __restrict__ W1, const float* __restrict__ b1,
                            const float* __restrict__ Whh) {
    int t = blockIdx.x * blockDim.x + threadIdx.x;
    int stride = gridDim.x * blockDim.x;
    for (int i = t; i < 64 * 256; i += stride) {
        int k = i >> 8, j = i & 255;
        float v = (j < 128) ? W1[j * 129 + k] : W1[(j - 128) * 129 + 64 + k];
        g_Wpre[((k >> 1) * 256 + j) * 2 + (k & 1)] = v;
    }
    for (int j = t; j < 256; j += stride) g_b1ext[j] = (j < 128) ? b1[j] : 0.f;
    for (int j = t; j < 128; j += stride) g_w1e[j] = W1[j * 129 + 128];
    for (int i = t; i < 64 * 192; i += stride) {
        int k = i / 192, j = i % 192;
        g_Whht[((k >> 1) * 192 + j) * 2 + (k & 1)] = Whh[j * 64 + k];
    }
}

// Wc[k,c] = sum_j W2[j,k] * Wih[c,j];  bc[c] = sum_j b2[j] * Wih[c,j]
__global__ void prep2_kernel(const float* __restrict__ W2, const float* __restrict__ b2,
                             const float* __restrict__ Wih) {
    int i = blockIdx.x * blockDim.x + threadIdx.x;
    if (i < 128 * 192) {
        int k = i / 192, c = i % 192;
        float acc = 0.f;
        #pragma unroll 8
        for (int j = 0; j < 64; ++j) acc = fmaf(W2[j * 128 + k], Wih[c * 64 + j], acc);
        g_Wc[((k >> 1) * 192 + c) * 2 + (k & 1)] = acc;
    }
    if (i < 192) {
        float acc = 0.f;
        #pragma unroll 8
        for (int j = 0; j < 64; ++j) acc = fmaf(b2[j], Wih[i * 64 + j], acc);
        g_bc[i] = acc;
    }
}

// ---------------- CSR build ----------------
__global__ void zero_cnt_kernel() {
    int t = blockIdx.x * blockDim.x + threadIdx.x;
    if (t < NN) g_cnt[t] = 0;
}

__global__ void hist_kernel(const int* __restrict__ ei, int E) {
    int e = blockIdx.x * blockDim.x + threadIdx.x;
    if (e < E) atomicAdd(&g_cnt[ei[E + e]], 1);
}

// pass 1: per-block (4096 elems) exclusive scan -> g_off (local), block total -> g_bsum
__global__ void scan1_kernel() {
    __shared__ int warpsums[32];
    const int tid = threadIdx.x;
    const int lane = tid & 31, warp = tid >> 5;
    const int idx = blockIdx.x * 4096 + tid * 4;
    int v0 = 0, v1 = 0, v2 = 0, v3 = 0;
    if (idx + 3 < NN) {
        int4 v = *reinterpret_cast<const int4*>(&g_cnt[idx]);
        v0 = v.x; v1 = v.y; v2 = v.z; v3 = v.w;
    } else {
        if (idx + 0 < NN) v0 = g_cnt[idx + 0];
        if (idx + 1 < NN) v1 = g_cnt[idx + 1];
        if (idx + 2 < NN) v2 = g_cnt[idx + 2];
        if (idx + 3 < NN) v3 = g_cnt[idx + 3];
    }
    int s0 = v0, s1 = s0 + v1, s2 = s1 + v2, s3 = s2 + v3;
    int incl = s3;
    #pragma unroll
    for (int o = 1; o < 32; o <<= 1) {
        int tt = __shfl_up_sync(0xffffffffu, incl, o);
        if (lane >= o) incl += tt;
    }
    if (lane == 31) warpsums[warp] = incl;
    __syncthreads();
    if (warp == 0) {
        int ws = warpsums[lane];
        #pragma unroll
        for (int o = 1; o < 32; o <<= 1) {
            int tt = __shfl_up_sync(0xffffffffu, ws, o);
            if (lane >= o) ws += tt;
        }
        warpsums[lane] = ws;
    }
    __syncthreads();
    int warpbase = (warp == 0) ? 0 : warpsums[warp - 1];
    int texcl = incl - s3 + warpbase;
    if (idx + 0 < NN) g_off[idx + 0] = texcl;
    if (idx + 1 < NN) g_off[idx + 1] = texcl + s0;
    if (idx + 2 < NN) g_off[idx + 2] = texcl + s1;
    if (idx + 3 < NN) g_off[idx + 3] = texcl + s2;
    if (tid == 1023) g_bsum[blockIdx.x] = warpsums[31];
}

// pass 2: scan the 25 block sums (one warp)
__global__ void scan2_kernel() {
    const int lane = threadIdx.x;
    int v = (lane < NB_SCAN) ? g_bsum[lane] : 0;
    int incl = v;
    #pragma unroll
    for (int o = 1; o < 32; o <<= 1) {
        int tt = __shfl_up_sync(0xffffffffu, incl, o);
        if (lane >= o) incl += tt;
    }
    if (lane < NB_SCAN) g_bexcl[lane] = incl - v;
    if (lane == 31) g_off[NN] = incl;
}

// pass 3: add block offsets, copy to g_cur
__global__ void scan3_kernel() {
    int i = blockIdx.x * blockDim.x + threadIdx.x;
    if (i < NN) {
        int v = g_off[i] + g_bexcl[i >> 12];
        g_off[i] = v;
        g_cur[i] = v;
    }
}

__global__ void scatter_kernel(const int* __restrict__ ei, const float* __restrict__ ea, int E) {
    int e = blockIdx.x * blockDim.x + threadIdx.x;
    if (e >= E) return;
    int dst = ei[E + e];
    int p = atomicAdd(&g_cur[dst], 1);
    g_epack[p] = make_int2(ei[e], __float_as_int(ea[e]));
}

// ---------------- aggregation: one warp per dst, no atomics ----------------
__global__ void agg_kernel() {
    const int dst = blockIdx.x * 8 + (threadIdx.x >> 5);
    if (dst >= NN) return;
    const int lane = threadIdx.x & 31;
    const int start = g_off[dst], end = g_off[dst + 1];
    const float4* AB4 = reinterpret_cast<const float4*>(g_AB);
    const float4 b = AB4[(size_t)dst * 64 + 32 + lane];
    const float4 w = reinterpret_cast<const float4*>(g_w1e)[lane];
    float4 acc = make_float4(0.f, 0.f, 0.f, 0.f);
    int e = start;
    for (; e + 1 < end; e += 2) {
        const int2 e0 = g_epack[e], e1 = g_epack[e + 1];
        const float t0 = __int_as_float(e0.y), t1 = __int_as_float(e1.y);
        const float4 a0 = AB4[(size_t)e0.x * 64 + lane];
        const float4 a1 = AB4[(size_t)e1.x * 64 + lane];
        acc.x += fmaxf(fmaf(t0, w.x, a0.x + b.x), 0.f) + fmaxf(fmaf(t1, w.x, a1.x + b.x), 0.f);
        acc.y += fmaxf(fmaf(t0, w.y, a0.y + b.y), 0.f) + fmaxf(fmaf(t1, w.y, a1.y + b.y), 0.f);
        acc.z += fmaxf(fmaf(t0, w.z, a0.z + b.z), 0.f) + fmaxf(fmaf(t1, w.z, a1.z + b.z), 0.f);
        acc.w += fmaxf(fmaf(t0, w.w, a0.w + b.w), 0.f) + fmaxf(fmaf(t1, w.w, a1.w + b.w), 0.f);
    }
    if (e < end) {
        const int2 e0 = g_epack[e];
        const float t0 = __int_as_float(e0.y);
        const float4 a0 = AB4[(size_t)e0.x * 64 + lane];
        acc.x += fmaxf(fmaf(t0, w.x, a0.x + b.x), 0.f);
        acc.y += fmaxf(fmaf(t0, w.y, a0.y + b.y), 0.f);
        acc.z += fmaxf(fmaf(t0, w.z, a0.z + b.z), 0.f);
        acc.w += fmaxf(fmaf(t0, w.w, a0.w + b.w), 0.f);
    }
    reinterpret_cast<float4*>(g_Hagg)[(size_t)dst * 32 + lane] = acc;
    if (lane == 0) g_degf[dst] = (float)(end - start);
}

// ---------------- persistent gemm1: AB[M,256] = x[M,64] @ Wpre + b1ext ----------------
// MT=32, NT=256, KK=64, TM=8, TN=4, TCOLS=64, TROWS=4, 256 threads.
// Weights stay in smem for the whole kernel; A-tiles register-prefetched.
__launch_bounds__(256, 2)
__global__ void gemm1_kernel(const float* __restrict__ A, float* __restrict__ C, int M) {
    constexpr int MT = 32, NT = 256, KK = 64, TM = 8, TN = 4, TCOLS = 64;
    extern __shared__ float smem[];
    float* As = smem;            // 32x64
    float* Ws = smem + MT * KK;  // 64x256 interleaved

    const int tid = threadIdx.x;
    {
        const float4* Wg = reinterpret_cast<const float4*>(g_Wpre);
        float4* Ws4 = reinterpret_cast<float4*>(Ws);
        #pragma unroll 4
        for (int i = tid; i < KK * NT / 4; i += 256) Ws4[i] = Wg[i];
    }
    const int tcol = tid % TCOLS;
    const int trow = tid / TCOLS;
    const float bias0 = g_b1ext[tcol];
    const float bias1 = g_b1ext[tcol + 64];
    const float bias2 = g_b1ext[tcol + 128];
    const float bias3 = g_b1ext[tcol + 192];

    const int stride = gridDim.x * MT;
    int m0 = blockIdx.x * MT;
    // first tile
    {
        const float4* Ag = reinterpret_cast<const float4*>(A) + (size_t)m0 * (KK / 4);
        float4* As4 = reinterpret_cast<float4*>(As);
        #pragma unroll
        for (int i = 0; i < 2; ++i) {
            int idx = tid + i * 256;
            As4[idx] = (m0 * (KK / 4) + idx < M * (KK / 4)) ? Ag[idx]
                       : make_float4(0.f, 0.f, 0.f, 0.f);
        }
    }
    __syncthreads();

    for (; m0 < M; m0 += stride) {
        const int mn = m0 + stride;
        float4 pre[2];
        if (mn < M) {
            const float4* Ag = reinterpret_cast<const float4*>(A) + (size_t)mn * (KK / 4);
            #pragma unroll
            for (int i = 0; i < 2; ++i) {
                int idx = tid + i * 256;
                pre[i] = (mn * (KK / 4) + idx < M * (KK / 4)) ? Ag[idx]
                         : make_float4(0.f, 0.f, 0.f, 0.f);
            }
        }

        ull acc[TM][TN];
        #pragma unroll
        for (int r = 0; r < TM; ++r)
            #pragma unroll
            for (int c = 0; c < TN; ++c) acc[r][c] = 0ull;

        const ull* As2 = reinterpret_cast<const ull*>(As) + (trow * TM) * (KK / 2);
        const ull* Ws2 = reinterpret_cast<const ull*>(Ws) + tcol;
        #pragma unroll 4
        for (int k2 = 0; k2 < KK / 2; ++k2) {
            ull a2[TM], w2[TN];
            #pragma unroll
            for (int r = 0; r < TM; ++r) a2[r] = As2[r * (KK / 2) + k2];
            #pragma unroll
            for (int c = 0; c < TN; ++c) w2[c] = Ws2[k2 * NT + c * TCOLS];
            #pragma unroll
            for (int r = 0; r < TM; ++r)
                #pragma unroll
                for (int c = 0; c < TN; ++c) ffma2(acc[r][c], a2[r], w2[c]);
        }

        #pragma unroll
        for (int r = 0; r < TM; ++r) {
            const int m = m0 + trow * TM + r;
            if (m < M) {
                float* crow = C + (size_t)m * NT;
                crow[tcol]       = unpack_sum(acc[r][0]) + bias0;
                crow[tcol + 64]  = unpack_sum(acc[r][1]) + bias1;
                crow[tcol + 128] = unpack_sum(acc[r][2]) + bias2;
                crow[tcol + 192] = unpack_sum(acc[r][3]) + bias3;
            }
        }

        __syncthreads();
        if (mn < M) {
            float4* As4 = reinterpret_cast<float4*>(As);
            #pragma unroll
            for (int i = 0; i < 2; ++i) As4[tid + i * 256] = pre[i];
        }
        __syncthreads();
    }
}

// ---------------- persistent fused GRU ----------------
// gi = Hagg[M,128] @ Wc[128,192] + deg*bc + bih ; gh = x[M,64] @ Whh^T[64,192] + bhh
// out = (1-z)*n + z*x.  MT=32, TM=8, TCOLS=64, TROWS=4, 256 threads.
__launch_bounds__(256, 1)
__global__ void gru_kernel(const float* __restrict__ X,
                           const float* __restrict__ bih, const float* __restrict__ bhh,
                           float* __restrict__ out, int M) {
    constexpr int MT = 32, NT = 192, TM = 8, TCOLS = 64;
    extern __shared__ float smem[];
    float* Hs = smem;                    // 32x128
    float* Xs = smem + MT * 128;         // 32x64
    float* Wc = smem + MT * 192;         // 128x192 interleaved
    float* Wh = Wc + 128 * 192;          // 64x192 interleaved

    const int tid = threadIdx.x;
    {
        const float4* Wcg = reinterpret_cast<const float4*>(g_Wc);
        const float4* Whg = reinterpret_cast<const float4*>(g_Whht);
        float4* Wc4 = reinterpret_cast<float4*>(Wc);
        float4* Wh4 = reinterpret_cast<float4*>(Wh);
        #pragma unroll 4
        for (int i = tid; i < 128 * 192 / 4; i += 256) Wc4[i] = Wcg[i];
        #pragma unroll 2
        for (int i = tid; i < 64 * 192 / 4; i += 256) Wh4[i] = Whg[i];
    }
    const int tcol = tid % TCOLS;
    const int trow = tid / TCOLS;
    const float bihr = bih[tcol],      bhhr = bhh[tcol];
    const float bihz = bih[tcol + 64], bhhz = bhh[tcol + 64];
    const float bihn = bih[tcol + 128], bhhn = bhh[tcol + 128];
    const float bcr = g_bc[tcol], bcz = g_bc[tcol + 64], bcn = g_bc[tcol + 128];

    const float4* Hg = reinterpret_cast<const float4*>(g_Hagg);
    const float4* Xg = reinterpret_cast<const float4*>(X);
    float4* Hs4 = reinterpret_cast<float4*>(Hs);
    float4* Xs4 = reinterpret_cast<float4*>(Xs);

    const int stride = gridDim.x * MT;
    int m0 = blockIdx.x * MT;
    {   // first tile
        #pragma unroll
        for (int i = 0; i < 4; ++i) {
            int idx = tid + i * 256;
            Hs4[idx] = ((size_t)m0 * 32 + idx < (size_t)M * 32) ? Hg[(size_t)m0 * 32 + idx]
                       : make_float4(0.f, 0.f, 0.f, 0.f);
        }
        #pragma unroll
        for (int i = 0; i < 2; ++i) {
            int idx = tid + i * 256;
            Xs4[idx] = ((size_t)m0 * 16 + idx < (size_t)M * 16) ? Xg[(size_t)m0 * 16 + idx]
                       : make_float4(0.f, 0.f, 0.f, 0.f);
        }
    }
    __syncthreads();

    for (; m0 < M; m0 += stride) {
        const int mn = m0 + stride;
        float4 preH[4], preX[2];
        if (mn < M) {
            #pragma unroll
            for (int i = 0; i < 4; ++i) {
                int idx = tid + i * 256;
                preH[i] = ((size_t)mn * 32 + idx < (size_t)M * 32) ? Hg[(size_t)mn * 32 + idx]
                          : make_float4(0.f, 0.f, 0.f, 0.f);
            }
            #pragma unroll
            for (int i = 0; i < 2; ++i) {
                int idx = tid + i * 256;
                preX[i] = ((size_t)mn * 16 + idx < (size_t)M * 16) ? Xg[(size_t)mn * 16 + idx]
                          : make_float4(0.f, 0.f, 0.f, 0.f);
            }
        }

        // phase 1: gh = Xs @ Wh  (K=64)
        float ghv[TM][3];
        {
            ull acc[TM][3];
            #pragma unroll
            for (int r = 0; r < TM; ++r)
                #pragma unroll
                for (int c = 0; c < 3; ++c) acc[r][c] = 0ull;
            const ull* Xs2 = reinterpret_cast<const ull*>(Xs) + (trow * TM) * 32;
            const ull* Wh2 = reinterpret_cast<const ull*>(Wh) + tcol;
            #pragma unroll 4
            for (int k2 = 0; k2 < 32; ++k2) {
                ull x2[TM], w2[3];
                #pragma unroll
                for (int r = 0; r < TM; ++r) x2[r] = Xs2[r * 32 + k2];
                #pragma unroll
                for (int c = 0; c < 3; ++c) w2[c] = Wh2[k2 * NT + c * TCOLS];
                #pragma unroll
                for (int r = 0; r < TM; ++r)
                    #pragma unroll
                    for (int c = 0; c < 3; ++c) ffma2(acc[r][c], x2[r], w2[c]);
            }
            #pragma unroll
            for (int r = 0; r < TM; ++r) {
                ghv[r][0] = unpack_sum(acc[r][0]) + bhhr;
                ghv[r][1] = unpack_sum(acc[r][1]) + bhhz;
                ghv[r][2] = unpack_sum(acc[r][2]) + bhhn;
            }
        }
        // phase 2: gi = Hs @ Wc  (K=128) + epilogue
        {
            ull acc[TM][3];
            #pragma unroll
            for (int r = 0; r < TM; ++r)
                #pragma unroll
                for (int c = 0; c < 3; ++c) acc[r][c] = 0ull;
            const ull* Hs2 = reinterpret_cast<const ull*>(Hs) + (trow * TM) * 64;
            const ull* Wc2 = reinterpret_cast<const ull*>(Wc) + tcol;
            #pragma unroll 4
            for (int k2 = 0; k2 < 64; ++k2) {
                ull h2[TM], w2[3];
                #pragma unroll
                for (int r = 0; r < TM; ++r) h2[r] = Hs2[r * 64 + k2];
                #pragma unroll
                for (int c = 0; c < 3; ++c) w2[c] = Wc2[k2 * NT + c * TCOLS];
                #pragma unroll
                for (int r = 0; r < TM; ++r)
                    #pragma unroll
                    for (int c = 0; c < 3; ++c) ffma2(acc[r][c], h2[r], w2[c]);
            }
            #pragma unroll
            for (int r = 0; r < TM; ++r) {
                const int m = m0 + trow * TM + r;
                if (m < M) {
                    const float deg = g_degf[m];
                    const float ir = unpack_sum(acc[r][0]) + fmaf(deg, bcr, bihr);
                    const float iz = unpack_sum(acc[r][1]) + fmaf(deg, bcz, bihz);
                    const float in_ = unpack_sum(acc[r][2]) + fmaf(deg, bcn, bihn);
                    const float rg = 1.f / (1.f + __expf(-(ir + ghv[r][0])));
                    const float zg = 1.f / (1.f + __expf(-(iz + ghv[r][1])));
                    const float nv = tanhf(fmaf(rg, ghv[r][2], in_));
                    const float xv = Xs[(trow * TM + r) * 64 + tcol];
                    out[(size_t)m * 64 + tcol] = (1.f - zg) * nv + zg * xv;
                }
            }
        }

        __syncthreads();
        if (mn < M) {
            #pragma unroll
            for (int i = 0; i < 4; ++i) Hs4[tid + i * 256] = preH[i];
            #pragma unroll
            for (int i = 0; i < 2; ++i) Xs4[tid + i * 256] = preX[i];
        }
        __syncthreads();
    }
}

// ---------------- launch ----------------
extern "C" void kernel_launch(void* const* d_in, const int* in_sizes, int n_in,
                              void* d_out, int out_size) {
    const float* x   = (const float*)d_in[0];
    const int*   ei  = (const int*)d_in[1];
    const float* ea  = (const float*)d_in[2];
    const float* W1  = (const float*)d_in[3];
    const float* b1  = (const float*)d_in[4];
    const float* W2  = (const float*)d_in[5];
    const float* b2  = (const float*)d_in[6];
    const float* Wih = (const float*)d_in[7];
    const float* bih = (const float*)d_in[8];
    const float* Whh = (const float*)d_in[9];
    const float* bhh = (const float*)d_in[10];
    float* out = (float*)d_out;

    const int M = in_sizes[0] / NDIM;  // 100000
    const int E = in_sizes[1] / 2;     // 1600000

    void* pAB;
    cudaGetSymbolAddress(&pAB, g_AB);

    constexpr int SM1 = (32 * 64 + 64 * 256) * 4;                    // 73728
    constexpr int SMG = (32 * 192 + 128 * 192 + 64 * 192) * 4;       // 172032
    cudaFuncSetAttribute(gemm1_kernel, cudaFuncAttributeMaxDynamicSharedMemorySize, SM1);
    cudaFuncSetAttribute(gru_kernel,   cudaFuncAttributeMaxDynamicSharedMemorySize, SMG);

    prep_kernel<<<64, 256>>>(W1, b1, Whh);
    prep2_kernel<<<96, 256>>>(W2, b2, Wih);
    zero_cnt_kernel<<<(NN + 255) / 256, 256>>>();
    hist_kernel<<<(E + 255) / 256, 256>>>(ei, E);

    // AB[N,256] = x @ Wpre + [b1|0]   (persistent, 2 CTAs/SM)
    gemm1_kernel<<<296, 256, SM1>>>(x, (float*)pAB, M);

    scan1_kernel<<<NB_SCAN, 1024>>>();
    scan2_kernel<<<1, 32>>>();
    scan3_kernel<<<(NN + 1023) / 1024, 1024>>>();
    scatter_kernel<<<(E + 255) / 256, 256>>>(ei, ea, E);

    // per-dst aggregation (no atomics)
    agg_kernel<<<(NN + 7) / 8, 256>>>();

    // fused: gi = Hagg@Wc + deg*bc + bih, gh = x@Whh^T + bhh, gates, out
    gru_kernel<<<148, 256, SMG>>>(x, bih, bhh, out, M);
}

// round 7
// speedup vs baseline: 1.1209x; 1.1209x over previous
#include <cuda_runtime.h>
#include <math.h>

// Fixed dataset shapes
#define NN 100000
#define EMAX 1600000
#define NDIM 64
#define NB_SCAN 25   // ceil(NN/4096)

typedef unsigned long long ull;

// ---------------- scratch ----------------
__device__ float g_A[NN * 128];       // per-node A = x@W1a^T + b1   (gathered by src; L2-resident)
__device__ float g_B[NN * 128];       // per-node B = x@W1b^T        (read once per dst)
__device__ float g_Hagg[NN * 128];    // per-dst sum of relu(hidden)
__device__ float g_degf[NN];          // in-degree (float)
__device__ float g_aggr[NN * 64];     // aggregated messages after W2
// CSR build
__device__ int   g_cnt[NN];
__device__ int   g_off[NN + 1];
__device__ int   g_cur[NN];
__device__ int   g_bsum[NB_SCAN];
__device__ int   g_bexcl[NB_SCAN];
__device__ int2  g_epack[EMAX];       // (src, bitcast attr)
// repacked weights (k-pair interleaved for f32x2: [(k>>1)*NT + c]*2 + (k&1))
__device__ float g_Wpre[64 * 256];
__device__ float g_b1ext[256];
__device__ float g_w1e[128];
__device__ float g_W2t[128 * 64];
__device__ float g_Wiht[64 * 192];
__device__ float g_Whht[64 * 192];

// ---------------- f32x2 helpers ----------------
__device__ __forceinline__ void ffma2(ull& d, ull a, ull b) {
    asm("fma.rn.f32x2 %0, %1, %2, %0;" : "+l"(d) : "l"(a), "l"(b));
}
__device__ __forceinline__ float unpack_sum(ull v) {
    float lo, hi;
    asm("mov.b64 {%0, %1}, %2;" : "=f"(lo), "=f"(hi) : "l"(v));
    return lo + hi;
}

// ---------------- weight repack ----------------
__global__ void prep_kernel(const float* __restrict__ W1, const float* __restrict__ b1,
                            const float* __restrict__ W2,
                            const float* __restrict__ Wih, const float* __restrict__ Whh) {
    int t = blockIdx.x * blockDim.x + threadIdx.x;
    int stride = gridDim.x * blockDim.x;
    for (int i = t; i < 64 * 256; i += stride) {
        int k = i >> 8, j = i & 255;
        float v = (j < 128) ? W1[j * 129 + k] : W1[(j - 128) * 129 + 64 + k];
        g_Wpre[((k >> 1) * 256 + j) * 2 + (k & 1)] = v;
    }
    for (int j = t; j < 256; j += stride) g_b1ext[j] = (j < 128) ? b1[j] : 0.f;
    for (int j = t; j < 128; j += stride) g_w1e[j] = W1[j * 129 + 128];
    for (int i = t; i < 128 * 64; i += stride) {
        int k = i >> 6, j = i & 63;
        g_W2t[((k >> 1) * 64 + j) * 2 + (k & 1)] = W2[j * 128 + k];
    }
    for (int i = t; i < 64 * 192; i += stride) {
        int k = i / 192, j = i % 192;
        g_Wiht[((k >> 1) * 192 + j) * 2 + (k & 1)] = Wih[j * 64 + k];
        g_Whht[((k >> 1) * 192 + j) * 2 + (k & 1)] = Whh[j * 64 + k];
    }
}

// ---------------- CSR build ----------------
__global__ void zero_cnt_kernel() {
    int t = blockIdx.x * blockDim.x + threadIdx.x;
    if (t < NN) g_cnt[t] = 0;
}

__global__ void hist_kernel(const int* __restrict__ ei, int E) {
    int e = blockIdx.x * blockDim.x + threadIdx.x;
    if (e < E) atomicAdd(&g_cnt[ei[E + e]], 1);
}

// pass 1: per-block (4096 elems) exclusive scan -> g_off (local), block total -> g_bsum
__global__ void scan1_kernel() {
    __shared__ int warpsums[32];
    const int tid = threadIdx.x;
    const int lane = tid & 31, warp = tid >> 5;
    const int idx = blockIdx.x * 4096 + tid * 4;
    int v0 = 0, v1 = 0, v2 = 0, v3 = 0;
    if (idx + 3 < NN) {
        int4 v = *reinterpret_cast<const int4*>(&g_cnt[idx]);
        v0 = v.x; v1 = v.y; v2 = v.z; v3 = v.w;
    } else {
        if (idx + 0 < NN) v0 = g_cnt[idx + 0];
        if (idx + 1 < NN) v1 = g_cnt[idx + 1];
        if (idx + 2 < NN) v2 = g_cnt[idx + 2];
        if (idx + 3 < NN) v3 = g_cnt[idx + 3];
    }
    int s0 = v0, s1 = s0 + v1, s2 = s1 + v2, s3 = s2 + v3;
    int incl = s3;
    #pragma unroll
    for (int o = 1; o < 32; o <<= 1) {
        int tt = __shfl_up_sync(0xffffffffu, incl, o);
        if (lane >= o) incl += tt;
    }
    if (lane == 31) warpsums[warp] = incl;
    __syncthreads();
    if (warp == 0) {
        int ws = warpsums[lane];
        #pragma unroll
        for (int o = 1; o < 32; o <<= 1) {
            int tt = __shfl_up_sync(0xffffffffu, ws, o);
            if (lane >= o) ws += tt;
        }
        warpsums[lane] = ws;
    }
    __syncthreads();
    int warpbase = (warp == 0) ? 0 : warpsums[warp - 1];
    int texcl = incl - s3 + warpbase;
    if (idx + 0 < NN) g_off[idx + 0] = texcl;
    if (idx + 1 < NN) g_off[idx + 1] = texcl + s0;
    if (idx + 2 < NN) g_off[idx + 2] = texcl + s1;
    if (idx + 3 < NN) g_off[idx + 3] = texcl + s2;
    if (tid == 1023) g_bsum[blockIdx.x] = warpsums[31];
}

// pass 2: scan the 25 block sums (one warp)
__global__ void scan2_kernel() {
    const int lane = threadIdx.x;
    int v = (lane < NB_SCAN) ? g_bsum[lane] : 0;
    int incl = v;
    #pragma unroll
    for (int o = 1; o < 32; o <<= 1) {
        int tt = __shfl_up_sync(0xffffffffu, incl, o);
        if (lane >= o) incl += tt;
    }
    if (lane < NB_SCAN) g_bexcl[lane] = incl - v;
    if (lane == 31) g_off[NN] = incl;
}

// pass 3: add block offsets, copy to g_cur
__global__ void scan3_kernel() {
    int i = blockIdx.x * blockDim.x + threadIdx.x;
    if (i < NN) {
        int v = g_off[i] + g_bexcl[i >> 12];
        g_off[i] = v;
        g_cur[i] = v;
    }
}

__global__ void scatter_kernel(const int* __restrict__ ei, const float* __restrict__ ea, int E) {
    int e = blockIdx.x * blockDim.x + threadIdx.x;
    if (e >= E) return;
    int dst = ei[E + e];
    int p = atomicAdd(&g_cur[dst], 1);
    g_epack[p] = make_int2(ei[e], __float_as_int(ea[e]));
}

// ---------------- aggregation: one warp per dst, no atomics ----------------
// Gather footprint = g_A (51 MB) -> L2-resident. 4-edge unroll for MLP=4.
__global__ void agg_kernel() {
    const int dst = blockIdx.x * 8 + (threadIdx.x >> 5);
    if (dst >= NN) return;
    const int lane = threadIdx.x & 31;
    const int start = g_off[dst], end = g_off[dst + 1];
    const float4* A4 = reinterpret_cast<const float4*>(g_A);
    const float4 b = reinterpret_cast<const float4*>(g_B)[(size_t)dst * 32 + lane];
    const float4 w = reinterpret_cast<const float4*>(g_w1e)[lane];
    float4 acc = make_float4(0.f, 0.f, 0.f, 0.f);
    int e = start;
    for (; e + 3 < end; e += 4) {
        int2 ep[4];
        float4 a[4];
        #pragma unroll
        for (int i = 0; i < 4; ++i) ep[i] = g_epack[e + i];
        #pragma unroll
        for (int i = 0; i < 4; ++i) a[i] = A4[(size_t)ep[i].x * 32 + lane];
        #pragma unroll
        for (int i = 0; i < 4; ++i) {
            const float t = __int_as_float(ep[i].y);
            acc.x += fmaxf(fmaf(t, w.x, a[i].x + b.x), 0.f);
            acc.y += fmaxf(fmaf(t, w.y, a[i].y + b.y), 0.f);
            acc.z += fmaxf(fmaf(t, w.z, a[i].z + b.z), 0.f);
            acc.w += fmaxf(fmaf(t, w.w, a[i].w + b.w), 0.f);
        }
    }
    for (; e < end; ++e) {
        const int2 e0 = g_epack[e];
        const float t0 = __int_as_float(e0.y);
        const float4 a0 = A4[(size_t)e0.x * 32 + lane];
        acc.x += fmaxf(fmaf(t0, w.x, a0.x + b.x), 0.f);
        acc.y += fmaxf(fmaf(t0, w.y, a0.y + b.y), 0.f);
        acc.z += fmaxf(fmaf(t0, w.z, a0.z + b.z), 0.f);
        acc.w += fmaxf(fmaf(t0, w.w, a0.w + b.w), 0.f);
    }
    reinterpret_cast<float4*>(g_Hagg)[(size_t)dst * 32 + lane] = acc;
    if (lane == 0) g_degf[dst] = (float)(end - start);
}

// ---------------- gemm1: [A|B] = x @ Wpre + [b1|0], split epilogue ----------------
// MT=32, NT=256, KK=64, TM=8, TN=4, TCOLS=64, TROWS=4 (R3's measured config).
__launch_bounds__(256, 2)
__global__ void gemm1_kernel(const float* __restrict__ Ain, int M) {
    constexpr int MT = 32, NT = 256, KK = 64, TM = 8, TN = 4, TCOLS = 64;
    extern __shared__ float smem[];
    float* As = smem;            // 32x64
    float* Ws = smem + MT * KK;  // 64x256 interleaved

    const int tid = threadIdx.x;
    const int m0 = blockIdx.x * MT;
    {
        const float4* Ag = reinterpret_cast<const float4*>(Ain) + (size_t)m0 * (KK / 4);
        float4* As4 = reinterpret_cast<float4*>(As);
        int rows = M - m0; if (rows > MT) rows = MT;
        const int lim = rows * (KK / 4);
        #pragma unroll 2
        for (int i = tid; i < MT * KK / 4; i += 256)
            As4[i] = (i < lim) ? Ag[i] : make_float4(0.f, 0.f, 0.f, 0.f);
        const float4* Wg = reinterpret_cast<const float4*>(g_Wpre);
        float4* Ws4 = reinterpret_cast<float4*>(Ws);
        #pragma unroll 4
        for (int i = tid; i < KK * NT / 4; i += 256) Ws4[i] = Wg[i];
    }
    __syncthreads();

    const int tcol = tid % TCOLS;
    const int trow = tid / TCOLS;
    ull acc[TM][TN];
    #pragma unroll
    for (int r = 0; r < TM; ++r)
        #pragma unroll
        for (int c = 0; c < TN; ++c) acc[r][c] = 0ull;

    const ull* As2 = reinterpret_cast<const ull*>(As) + (trow * TM) * (KK / 2);
    const ull* Ws2 = reinterpret_cast<const ull*>(Ws) + tcol;
    #pragma unroll 4
    for (int k2 = 0; k2 < KK / 2; ++k2) {
        ull a2[TM], w2[TN];
        #pragma unroll
        for (int r = 0; r < TM; ++r) a2[r] = As2[r * (KK / 2) + k2];
        #pragma unroll
        for (int c = 0; c < TN; ++c) w2[c] = Ws2[k2 * NT + c * TCOLS];
        #pragma unroll
        for (int r = 0; r < TM; ++r)
            #pragma unroll
            for (int c = 0; c < TN; ++c) ffma2(acc[r][c], a2[r], w2[c]);
    }

    const float bias0 = g_b1ext[tcol];
    const float bias1 = g_b1ext[tcol + 64];
    #pragma unroll
    for (int r = 0; r < TM; ++r) {
        const int m = m0 + trow * TM + r;
        if (m < M) {
            float* arow = g_A + (size_t)m * 128;
            float* brow = g_B + (size_t)m * 128;
            arow[tcol]      = unpack_sum(acc[r][0]) + bias0;
            arow[tcol + 64] = unpack_sum(acc[r][1]) + bias1;
            brow[tcol]      = unpack_sum(acc[r][2]);
            brow[tcol + 64] = unpack_sum(acc[r][3]);
        }
    }
}

// ---------------- f32x2 GEMM (R3's): C[M,NT] = A[M,KK] @ W + bias (EPI1: rowscale*bias) ----------------
template <int MT, int NT, int KK, int TM, int TN, int EPI>
__launch_bounds__(256, 2)
__global__ void gemm_k(const float* __restrict__ A, const float* __restrict__ W,
                       const float* __restrict__ bias, const float* __restrict__ rowscale,
                       float* __restrict__ C, int M) {
    constexpr int TCOLS = NT / TN;
    constexpr int TROWS = MT / TM;
    static_assert(TCOLS * TROWS == 256, "bad tiling");
    extern __shared__ float smem[];
    float* As = smem;            // MT x KK
    float* Ws = smem + MT * KK;  // KK x NT (pair-interleaved)

    const int tid = threadIdx.x;
    const int m0 = blockIdx.x * MT;
    {
        const float4* Ag = reinterpret_cast<const float4*>(A) + (size_t)m0 * (KK / 4);
        float4* As4 = reinterpret_cast<float4*>(As);
        int rows = M - m0; if (rows > MT) rows = MT;
        const int lim = rows * (KK / 4);
        #pragma unroll 4
        for (int i = tid; i < MT * KK / 4; i += 256)
            As4[i] = (i < lim) ? Ag[i] : make_float4(0.f, 0.f, 0.f, 0.f);
        const float4* Wg = reinterpret_cast<const float4*>(W);
        float4* Ws4 = reinterpret_cast<float4*>(Ws);
        #pragma unroll 4
        for (int i = tid; i < KK * NT / 4; i += 256) Ws4[i] = Wg[i];
    }
    __syncthreads();

    const int tcol = tid % TCOLS;
    const int trow = tid / TCOLS;
    ull acc[TM][TN];
    #pragma unroll
    for (int r = 0; r < TM; ++r)
        #pragma unroll
        for (int c = 0; c < TN; ++c) acc[r][c] = 0ull;

    const ull* As2 = reinterpret_cast<const ull*>(As) + (trow * TM) * (KK / 2);
    const ull* Ws2 = reinterpret_cast<const ull*>(Ws) + tcol;

    #pragma unroll 4
    for (int k2 = 0; k2 < KK / 2; ++k2) {
        ull a2[TM], w2[TN];
        #pragma unroll
        for (int r = 0; r < TM; ++r) a2[r] = As2[r * (KK / 2) + k2];
        #pragma unroll
        for (int c = 0; c < TN; ++c) w2[c] = Ws2[k2 * NT + c * TCOLS];
        #pragma unroll
        for (int r = 0; r < TM; ++r)
            #pragma unroll
            for (int c = 0; c < TN; ++c) ffma2(acc[r][c], a2[r], w2[c]);
    }

    #pragma unroll
    for (int r = 0; r < TM; ++r) {
        const int m = m0 + trow * TM + r;
        if (m < M) {
            float rs = 1.f;
            if (EPI == 1) rs = rowscale[m];
            float* crow = C + (size_t)m * NT;
            #pragma unroll
            for (int c = 0; c < TN; ++c) {
                const int j = tcol + c * TCOLS;
                const float b = bias[j];
                crow[j] = unpack_sum(acc[r][c]) + ((EPI == 1) ? rs * b : b);
            }
        }
    }
}

// ---------------- fused GRU (R3's): dual f32x2 GEMM + gates epilogue ----------------
__launch_bounds__(256, 2)
__global__ void gru_kernel(const float* __restrict__ Aggr, const float* __restrict__ X,
                           const float* __restrict__ bih, const float* __restrict__ bhh,
                           float* __restrict__ out, int M) {
    constexpr int MT = 16, KK = 64, NT = 192, TM = 4, TCOLS = 64;
    extern __shared__ float smem[];
    float* As = smem;                 // 16x64 (aggr)
    float* Xs = smem + MT * KK;       // 16x64 (x)
    float* Wi = smem + 2 * MT * KK;   // 64x192 interleaved
    float* Wh = Wi + KK * NT;

    const int tid = threadIdx.x;
    const int m0 = blockIdx.x * MT;
    {
        int rows = M - m0; if (rows > MT) rows = MT;
        const int lim = rows * (KK / 4);
        const float4* Ag = reinterpret_cast<const float4*>(Aggr) + (size_t)m0 * (KK / 4);
        const float4* Xg = reinterpret_cast<const float4*>(X) + (size_t)m0 * (KK / 4);
        float4* As4 = reinterpret_cast<float4*>(As);
        float4* Xs4 = reinterpret_cast<float4*>(Xs);
        for (int i = tid; i < MT * KK / 4; i += 256) {
            As4[i] = (i < lim) ? Ag[i] : make_float4(0.f, 0.f, 0.f, 0.f);
            Xs4[i] = (i < lim) ? Xg[i] : make_float4(0.f, 0.f, 0.f, 0.f);
        }
        const float4* Wig = reinterpret_cast<const float4*>(g_Wiht);
        const float4* Whg = reinterpret_cast<const float4*>(g_Whht);
        float4* Wi4 = reinterpret_cast<float4*>(Wi);
        float4* Wh4 = reinterpret_cast<float4*>(Wh);
        #pragma unroll 4
        for (int i = tid; i < KK * NT / 4; i += 256) { Wi4[i] = Wig[i]; Wh4[i] = Whg[i]; }
    }
    __syncthreads();

    const int tcol = tid % TCOLS;
    const int trow = tid / TCOLS;
    ull gi[TM][3], gh[TM][3];
    #pragma unroll
    for (int r = 0; r < TM; ++r)
        #pragma unroll
        for (int c = 0; c < 3; ++c) { gi[r][c] = 0ull; gh[r][c] = 0ull; }

    const ull* As2 = reinterpret_cast<const ull*>(As) + (trow * TM) * (KK / 2);
    const ull* Xs2 = reinterpret_cast<const ull*>(Xs) + (trow * TM) * (KK / 2);
    const ull* Wi2 = reinterpret_cast<const ull*>(Wi) + tcol;
    const ull* Wh2 = reinterpret_cast<const ull*>(Wh) + tcol;

    #pragma unroll 4
    for (int k2 = 0; k2 < KK / 2; ++k2) {
        ull a2[TM], x2[TM], wi2[3], wh2[3];
        #pragma unroll
        for (int r = 0; r < TM; ++r) {
            a2[r] = As2[r * (KK / 2) + k2];
            x2[r] = Xs2[r * (KK / 2) + k2];
        }
        #pragma unroll
        for (int c = 0; c < 3; ++c) {
            wi2[c] = Wi2[k2 * NT + c * TCOLS];
            wh2[c] = Wh2[k2 * NT + c * TCOLS];
        }
        #pragma unroll
        for (int r = 0; r < TM; ++r)
            #pragma unroll
            for (int c = 0; c < 3; ++c) {
                ffma2(gi[r][c], a2[r], wi2[c]);
                ffma2(gh[r][c], x2[r], wh2[c]);
            }
    }

    const float bir = bih[tcol],      bhr = bhh[tcol];
    const float biz = bih[tcol + 64], bhz = bhh[tcol + 64];
    const float bin = bih[tcol + 128], bhn = bhh[tcol + 128];
    #pragma unroll
    for (int r = 0; r < TM; ++r) {
        const int m = m0 + trow * TM + r;
        if (m < M) {
            const float ir = unpack_sum(gi[r][0]) + bir;
            const float hr = unpack_sum(gh[r][0]) + bhr;
            const float iz = unpack_sum(gi[r][1]) + biz;
            const float hz = unpack_sum(gh[r][1]) + bhz;
            const float in_ = unpack_sum(gi[r][2]) + bin;
            const float hn = unpack_sum(gh[r][2]) + bhn;
            const float rg = 1.f / (1.f + __expf(-(ir + hr)));
            const float zg = 1.f / (1.f + __expf(-(iz + hz)));
            const float nv = tanhf(fmaf(rg, hn, in_));
            const float xv = Xs[(trow * TM + r) * KK + tcol];
            out[(size_t)m * 64 + tcol] = (1.f - zg) * nv + zg * xv;
        }
    }
}

// ---------------- launch ----------------
extern "C" void kernel_launch(void* const* d_in, const int* in_sizes, int n_in,
                              void* d_out, int out_size) {
    const float* x   = (const float*)d_in[0];
    const int*   ei  = (const int*)d_in[1];
    const float* ea  = (const float*)d_in[2];
    const float* W1  = (const float*)d_in[3];
    const float* b1  = (const float*)d_in[4];
    const float* W2  = (const float*)d_in[5];
    const float* b2  = (const float*)d_in[6];
    const float* Wih = (const float*)d_in[7];
    const float* bih = (const float*)d_in[8];
    const float* Whh = (const float*)d_in[9];
    const float* bhh = (const float*)d_in[10];
    float* out = (float*)d_out;

    const int M = in_sizes[0] / NDIM;  // 100000
    const int E = in_sizes[1] / 2;     // 1600000

    void *pHagg, *pdeg, *paggr, *pW2t;
    cudaGetSymbolAddress(&pHagg, g_Hagg);
    cudaGetSymbolAddress(&pdeg,  g_degf);
    cudaGetSymbolAddress(&paggr, g_aggr);
    cudaGetSymbolAddress(&pW2t,  g_W2t);

    constexpr int SM1 = (32 * 64 + 64 * 256) * 4;          // 73728
    constexpr int SM2 = (64 * 128 + 128 * 64) * 4;         // 65536
    constexpr int SMG = (2 * 16 * 64 + 2 * 64 * 192) * 4;  // 106496
    cudaFuncSetAttribute(gemm1_kernel, cudaFuncAttributeMaxDynamicSharedMemorySize, SM1);
    cudaFuncSetAttribute(gemm_k<64, 64, 128, 8, 2, 1>,
                         cudaFuncAttributeMaxDynamicSharedMemorySize, SM2);
    cudaFuncSetAttribute(gru_kernel, cudaFuncAttributeMaxDynamicSharedMemorySize, SMG);

    prep_kernel<<<64, 256>>>(W1, b1, W2, Wih, Whh);
    zero_cnt_kernel<<<(NN + 255) / 256, 256>>>();
    hist_kernel<<<(E + 255) / 256, 256>>>(ei, E);

    // A/B split: A = x@W1a^T + b1 (gather target), B = x@W1b^T
    gemm1_kernel<<<(M + 31) / 32, 256, SM1>>>(x, M);

    scan1_kernel<<<NB_SCAN, 1024>>>();
    scan2_kernel<<<1, 32>>>();
    scan3_kernel<<<(NN + 1023) / 1024, 1024>>>();
    scatter_kernel<<<(E + 255) / 256, 256>>>(ei, ea, E);

    // per-dst aggregation (no atomics; gather from L2-resident g_A)
    agg_kernel<<<(NN + 7) / 8, 256>>>();

    // aggr[N,64] = Hagg @ W2t + deg * b2
    gemm_k<64, 64, 128, 8, 2, 1><<<(M + 63) / 64, 256, SM2>>>(
        (const float*)pHagg, (const float*)pW2t, b2, (const float*)pdeg, (float*)paggr, M);

    // fused: gi = aggr@Wih^T+bih, gh = x@Whh^T+bhh, GRU gates, write out
    gru_kernel<<<(M + 15) / 16, 256, SMG>>>(
        (const float*)paggr, x, bih, bhh, out, M);
}

// round 12
// speedup vs baseline: 1.1380x; 1.0152x over previous
#include <cuda_runtime.h>
#include <cuda_fp16.h>
#include <stdint.h>
#include <cstdint>
#include <math.h>

// Fixed dataset shapes
#define NN 100000
#define EMAX 1600000
#define NDIM 64
#define NB_SCAN 25   // ceil(NN/4096)

typedef unsigned long long ull;
typedef unsigned int u32;

// ---------------- scratch ----------------
__device__ __half g_Ah[NN * 128];     // per-node A = x@W1a^T + b1, fp16 (gather target; 26 MB)
__device__ float g_B[NN * 128];       // per-node B = x@W1b^T (read once per dst)
__device__ float g_Hagg[NN * 128];    // per-dst sum of relu(hidden)
__device__ float g_degf[NN];          // in-degree (float)
__device__ float g_aggr[NN * 64];     // aggregated messages after W2
// CSR build
__device__ int   g_cnt[NN];
__device__ int   g_off[NN + 1];
__device__ int   g_cur[NN];
__device__ int   g_bsum[NB_SCAN];
__device__ int   g_bexcl[NB_SCAN];
__device__ int2  g_epack[EMAX];       // (src, bitcast attr)
// repacked weights (k-pair interleaved for f32x2: [(k>>1)*NT + c]*2 + (k&1))
__device__ float g_Wpre[64 * 256];
__device__ float g_b1ext[256];
__device__ float g_w1e[128];
__device__ float g_W2t[128 * 64];
__device__ float g_Wiht[64 * 192];
__device__ float g_Whht[64 * 192];

// ---------------- f32x2 helpers ----------------
__device__ __forceinline__ void ffma2(ull& d, ull a, ull b) {
    asm("fma.rn.f32x2 %0, %1, %2, %0;" : "+l"(d) : "l"(a), "l"(b));
}
__device__ __forceinline__ float unpack_sum(ull v) {
    float lo, hi;
    asm("mov.b64 {%0, %1}, %2;" : "=f"(lo), "=f"(hi) : "l"(v));
    return lo + hi;
}

// ---------------- weight repack ----------------
__global__ void prep_kernel(const float* __restrict__ W1, const float* __restrict__ b1,
                            const float* __restrict__ W2,
                            const float* __restrict__ Wih, const float* __restrict__ Whh) {
    int t = blockIdx.x * blockDim.x + threadIdx.x;
    int stride = gridDim.x * blockDim.x;
    for (int i = t; i < 64 * 256; i += stride) {
        int k = i >> 8, j = i & 255;
        float v = (j < 128) ? W1[j * 129 + k] : W1[(j - 128) * 129 + 64 + k];
        g_Wpre[((k >> 1) * 256 + j) * 2 + (k & 1)] = v;
    }
    for (int j = t; j < 256; j += stride) g_b1ext[j] = (j < 128) ? b1[j] : 0.f;
    for (int j = t; j < 128; j += stride) g_w1e[j] = W1[j * 129 + 128];
    for (int i = t; i < 128 * 64; i += stride) {
        int k = i >> 6, j = i & 63;
        g_W2t[((k >> 1) * 64 + j) * 2 + (k & 1)] = W2[j * 128 + k];
    }
    for (int i = t; i < 64 * 192; i += stride) {
        int k = i / 192, j = i % 192;
        g_Wiht[((k >> 1) * 192 + j) * 2 + (k & 1)] = Wih[j * 64 + k];
        g_Whht[((k >> 1) * 192 + j) * 2 + (k & 1)] = Whh[j * 64 + k];
    }
}

// ---------------- CSR build ----------------
__global__ void zero_cnt_kernel() {
    int t = blockIdx.x * blockDim.x + threadIdx.x;
    if (t < NN) g_cnt[t] = 0;
}

__global__ void hist_kernel(const int* __restrict__ ei, int E) {
    int e = blockIdx.x * blockDim.x + threadIdx.x;
    if (e < E) atomicAdd(&g_cnt[ei[E + e]], 1);
}

__global__ void scan1_kernel() {
    __shared__ int warpsums[32];
    const int tid = threadIdx.x;
    const int lane = tid & 31, warp = tid >> 5;
    const int idx = blockIdx.x * 4096 + tid * 4;
    int v0 = 0, v1 = 0, v2 = 0, v3 = 0;
    if (idx + 3 < NN) {
        int4 v = *reinterpret_cast<const int4*>(&g_cnt[idx]);
        v0 = v.x; v1 = v.y; v2 = v.z; v3 = v.w;
    } else {
        if (idx + 0 < NN) v0 = g_cnt[idx + 0];
        if (idx + 1 < NN) v1 = g_cnt[idx + 1];
        if (idx + 2 < NN) v2 = g_cnt[idx + 2];
        if (idx + 3 < NN) v3 = g_cnt[idx + 3];
    }
    int s0 = v0, s1 = s0 + v1, s2 = s1 + v2, s3 = s2 + v3;
    int incl = s3;
    #pragma unroll
    for (int o = 1; o < 32; o <<= 1) {
        int tt = __shfl_up_sync(0xffffffffu, incl, o);
        if (lane >= o) incl += tt;
    }
    if (lane == 31) warpsums[warp] = incl;
    __syncthreads();
    if (warp == 0) {
        int ws = warpsums[lane];
        #pragma unroll
        for (int o = 1; o < 32; o <<= 1) {
            int tt = __shfl_up_sync(0xffffffffu, ws, o);
            if (lane >= o) ws += tt;
        }
        warpsums[lane] = ws;
    }
    __syncthreads();
    int warpbase = (warp == 0) ? 0 : warpsums[warp - 1];
    int texcl = incl - s3 + warpbase;
    if (idx + 0 < NN) g_off[idx + 0] = texcl;
    if (idx + 1 < NN) g_off[idx + 1] = texcl + s0;
    if (idx + 2 < NN) g_off[idx + 2] = texcl + s1;
    if (idx + 3 < NN) g_off[idx + 3] = texcl + s2;
    if (tid == 1023) g_bsum[blockIdx.x] = warpsums[31];
}

__global__ void scan2_kernel() {
    const int lane = threadIdx.x;
    int v = (lane < NB_SCAN) ? g_bsum[lane] : 0;
    int incl = v;
    #pragma unroll
    for (int o = 1; o < 32; o <<= 1) {
        int tt = __shfl_up_sync(0xffffffffu, incl, o);
        if (lane >= o) incl += tt;
    }
    if (lane < NB_SCAN) g_bexcl[lane] = incl - v;
    if (lane == 31) g_off[NN] = incl;
}

__global__ void scan3_kernel() {
    int i = blockIdx.x * blockDim.x + threadIdx.x;
    if (i < NN) {
        int v = g_off[i] + g_bexcl[i >> 12];
        g_off[i] = v;
        g_cur[i] = v;
    }
}

__global__ void scatter_kernel(const int* __restrict__ ei, const float* __restrict__ ea, int E) {
    int e = blockIdx.x * blockDim.x + threadIdx.x;
    if (e >= E) return;
    int dst = ei[E + e];
    int p = atomicAdd(&g_cur[dst], 1);
    g_epack[p] = make_int2(ei[e], __float_as_int(ea[e]));
}

// ---------------- aggregation: one warp per dst, no atomics ----------------
// A gathered in fp16 (256 B/edge instead of 512 B); B/w/accumulate in fp32.
__global__ void agg_kernel() {
    const int dst = blockIdx.x * 8 + (threadIdx.x >> 5);
    if (dst >= NN) return;
    const int lane = threadIdx.x & 31;
    const int start = g_off[dst], end = g_off[dst + 1];
    const uint2* Ah = reinterpret_cast<const uint2*>(g_Ah);   // 8 B = 4 halves per lane
    const float4 b = reinterpret_cast<const float4*>(g_B)[(size_t)dst * 32 + lane];
    const float4 w = reinterpret_cast<const float4*>(g_w1e)[lane];
    float4 acc = make_float4(0.f, 0.f, 0.f, 0.f);
    int e = start;
    for (; e + 7 < end; e += 8) {
        int2 ep[8];
        uint2 ap[8];
        #pragma unroll
        for (int i = 0; i < 8; ++i) ep[i] = g_epack[e + i];
        #pragma unroll
        for (int i = 0; i < 8; ++i) ap[i] = Ah[(size_t)ep[i].x * 32 + lane];
        #pragma unroll
        for (int i = 0; i < 8; ++i) {
            const float t = __int_as_float(ep[i].y);
            const float2 a01 = __half22float2(*reinterpret_cast<const __half2*>(&ap[i].x));
            const float2 a23 = __half22float2(*reinterpret_cast<const __half2*>(&ap[i].y));
            acc.x += fmaxf(fmaf(t, w.x, a01.x + b.x), 0.f);
            acc.y += fmaxf(fmaf(t, w.y, a01.y + b.y), 0.f);
            acc.z += fmaxf(fmaf(t, w.z, a23.x + b.z), 0.f);
            acc.w += fmaxf(fmaf(t, w.w, a23.y + b.w), 0.f);
        }
    }
    for (; e < end; ++e) {
        const int2 e0 = g_epack[e];
        const float t = __int_as_float(e0.y);
        const uint2 a = Ah[(size_t)e0.x * 32 + lane];
        const float2 a01 = __half22float2(*reinterpret_cast<const __half2*>(&a.x));
        const float2 a23 = __half22float2(*reinterpret_cast<const __half2*>(&a.y));
        acc.x += fmaxf(fmaf(t, w.x, a01.x + b.x), 0.f);
        acc.y += fmaxf(fmaf(t, w.y, a01.y + b.y), 0.f);
        acc.z += fmaxf(fmaf(t, w.z, a23.x + b.z), 0.f);
        acc.w += fmaxf(fmaf(t, w.w, a23.y + b.w), 0.f);
    }
    reinterpret_cast<float4*>(g_Hagg)[(size_t)dst * 32 + lane] = acc;
    if (lane == 0) g_degf[dst] = (float)(end - start);
}

// ---------------- gemm1 (R7 SIMT): [A(fp16)|B(fp32)] = x @ Wpre + [b1|0] ----------------
// MT=32, NT=256, KK=64, TM=8, TN=4, TCOLS=64, TROWS=4 (measured config).
__launch_bounds__(256, 2)
__global__ void gemm1_kernel(const float* __restrict__ Ain, int M) {
    constexpr int MT = 32, NT = 256, KK = 64, TM = 8, TN = 4, TCOLS = 64;
    extern __shared__ float smem[];
    float* As = smem;            // 32x64
    float* Ws = smem + MT * KK;  // 64x256 interleaved

    const int tid = threadIdx.x;
    const int m0 = blockIdx.x * MT;
    {
        const float4* Ag = reinterpret_cast<const float4*>(Ain) + (size_t)m0 * (KK / 4);
        float4* As4 = reinterpret_cast<float4*>(As);
        int rows = M - m0; if (rows > MT) rows = MT;
        const int lim = rows * (KK / 4);
        #pragma unroll 2
        for (int i = tid; i < MT * KK / 4; i += 256)
            As4[i] = (i < lim) ? Ag[i] : make_float4(0.f, 0.f, 0.f, 0.f);
        const float4* Wg = reinterpret_cast<const float4*>(g_Wpre);
        float4* Ws4 = reinterpret_cast<float4*>(Ws);
        #pragma unroll 4
        for (int i = tid; i < KK * NT / 4; i += 256) Ws4[i] = Wg[i];
    }
    __syncthreads();

    const int tcol = tid % TCOLS;
    const int trow = tid / TCOLS;
    ull acc[TM][TN];
    #pragma unroll
    for (int r = 0; r < TM; ++r)
        #pragma unroll
        for (int c = 0; c < TN; ++c) acc[r][c] = 0ull;

    const ull* As2 = reinterpret_cast<const ull*>(As) + (trow * TM) * (KK / 2);
    const ull* Ws2 = reinterpret_cast<const ull*>(Ws) + tcol;
    #pragma unroll 4
    for (int k2 = 0; k2 < KK / 2; ++k2) {
        ull a2[TM], w2[TN];
        #pragma unroll
        for (int r = 0; r < TM; ++r) a2[r] = As2[r * (KK / 2) + k2];
        #pragma unroll
        for (int c = 0; c < TN; ++c) w2[c] = Ws2[k2 * NT + c * TCOLS];
        #pragma unroll
        for (int r = 0; r < TM; ++r)
            #pragma unroll
            for (int c = 0; c < TN; ++c) ffma2(acc[r][c], a2[r], w2[c]);
    }

    const float bias0 = g_b1ext[tcol];
    const float bias1 = g_b1ext[tcol + 64];
    #pragma unroll
    for (int r = 0; r < TM; ++r) {
        const int m = m0 + trow * TM + r;
        if (m < M) {
            __half* ahrow = g_Ah + (size_t)m * 128;
            float* brow = g_B + (size_t)m * 128;
            ahrow[tcol]      = __float2half(unpack_sum(acc[r][0]) + bias0);
            ahrow[tcol + 64] = __float2half(unpack_sum(acc[r][1]) + bias1);
            brow[tcol]       = unpack_sum(acc[r][2]);
            brow[tcol + 64]  = unpack_sum(acc[r][3]);
        }
    }
}

// ---------------- f32x2 GEMM (R3/R7): C[M,NT] = A[M,KK] @ W + bias (EPI1: rowscale*bias) ----------------
template <int MT, int NT, int KK, int TM, int TN, int EPI>
__launch_bounds__(256, 2)
__global__ void gemm_k(const float* __restrict__ A, const float* __restrict__ W,
                       const float* __restrict__ bias, const float* __restrict__ rowscale,
                       float* __restrict__ C, int M) {
    constexpr int TCOLS = NT / TN;
    constexpr int TROWS = MT / TM;
    static_assert(TCOLS * TROWS == 256, "bad tiling");
    extern __shared__ float smemf[];
    float* As = smemf;
    float* Ws = smemf + MT * KK;

    const int tid = threadIdx.x;
    const int m0 = blockIdx.x * MT;
    {
        const float4* Ag = reinterpret_cast<const float4*>(A) + (size_t)m0 * (KK / 4);
        float4* As4 = reinterpret_cast<float4*>(As);
        int rows = M - m0; if (rows > MT) rows = MT;
        const int lim = rows * (KK / 4);
        #pragma unroll 4
        for (int i = tid; i < MT * KK / 4; i += 256)
            As4[i] = (i < lim) ? Ag[i] : make_float4(0.f, 0.f, 0.f, 0.f);
        const float4* Wg = reinterpret_cast<const float4*>(W);
        float4* Ws4 = reinterpret_cast<float4*>(Ws);
        #pragma unroll 4
        for (int i = tid; i < KK * NT / 4; i += 256) Ws4[i] = Wg[i];
    }
    __syncthreads();

    const int tcol = tid % TCOLS;
    const int trow = tid / TCOLS;
    ull acc[TM][TN];
    #pragma unroll
    for (int r = 0; r < TM; ++r)
        #pragma unroll
        for (int c = 0; c < TN; ++c) acc[r][c] = 0ull;

    const ull* As2 = reinterpret_cast<const ull*>(As) + (trow * TM) * (KK / 2);
    const ull* Ws2 = reinterpret_cast<const ull*>(Ws) + tcol;

    #pragma unroll 4
    for (int k2 = 0; k2 < KK / 2; ++k2) {
        ull a2[TM], w2[TN];
        #pragma unroll
        for (int r = 0; r < TM; ++r) a2[r] = As2[r * (KK / 2) + k2];
        #pragma unroll
        for (int c = 0; c < TN; ++c) w2[c] = Ws2[k2 * NT + c * TCOLS];
        #pragma unroll
        for (int r = 0; r < TM; ++r)
            #pragma unroll
            for (int c = 0; c < TN; ++c) ffma2(acc[r][c], a2[r], w2[c]);
    }

    #pragma unroll
    for (int r = 0; r < TM; ++r) {
        const int m = m0 + trow * TM + r;
        if (m < M) {
            float rs = 1.f;
            if (EPI == 1) rs = rowscale[m];
            float* crow = C + (size_t)m * NT;
            #pragma unroll
            for (int c = 0; c < TN; ++c) {
                const int j = tcol + c * TCOLS;
                const float b = bias[j];
                crow[j] = unpack_sum(acc[r][c]) + ((EPI == 1) ? rs * b : b);
            }
        }
    }
}

// ---------------- fused GRU (R3/R7): dual f32x2 GEMM + gates epilogue ----------------
__launch_bounds__(256, 2)
__global__ void gru_kernel(const float* __restrict__ Aggr, const float* __restrict__ X,
                           const float* __restrict__ bih, const float* __restrict__ bhh,
                           float* __restrict__ out, int M) {
    constexpr int MT = 16, KK = 64, NT = 192, TM = 4, TCOLS = 64;
    extern __shared__ float smemf[];
    float* As = smemf;
    float* Xs = smemf + MT * KK;
    float* Wi = smemf + 2 * MT * KK;
    float* Wh = Wi + KK * NT;

    const int tid = threadIdx.x;
    const int m0 = blockIdx.x * MT;
    {
        int rows = M - m0; if (rows > MT) rows = MT;
        const int lim = rows * (KK / 4);
        const float4* Ag = reinterpret_cast<const float4*>(Aggr) + (size_t)m0 * (KK / 4);
        const float4* Xg = reinterpret_cast<const float4*>(X) + (size_t)m0 * (KK / 4);
        float4* As4 = reinterpret_cast<float4*>(As);
        float4* Xs4 = reinterpret_cast<float4*>(Xs);
        for (int i = tid; i < MT * KK / 4; i += 256) {
            As4[i] = (i < lim) ? Ag[i] : make_float4(0.f, 0.f, 0.f, 0.f);
            Xs4[i] = (i < lim) ? Xg[i] : make_float4(0.f, 0.f, 0.f, 0.f);
        }
        const float4* Wig = reinterpret_cast<const float4*>(g_Wiht);
        const float4* Whg = reinterpret_cast<const float4*>(g_Whht);
        float4* Wi4 = reinterpret_cast<float4*>(Wi);
        float4* Wh4 = reinterpret_cast<float4*>(Wh);
        #pragma unroll 4
        for (int i = tid; i < KK * NT / 4; i += 256) { Wi4[i] = Wig[i]; Wh4[i] = Whg[i]; }
    }
    __syncthreads();

    const int tcol = tid % TCOLS;
    const int trow = tid / TCOLS;
    ull gi[TM][3], gh[TM][3];
    #pragma unroll
    for (int r = 0; r < TM; ++r)
        #pragma unroll
        for (int c = 0; c < 3; ++c) { gi[r][c] = 0ull; gh[r][c] = 0ull; }

    const ull* As2 = reinterpret_cast<const ull*>(As) + (trow * TM) * (KK / 2);
    const ull* Xs2 = reinterpret_cast<const ull*>(Xs) + (trow * TM) * (KK / 2);
    const ull* Wi2 = reinterpret_cast<const ull*>(Wi) + tcol;
    const ull* Wh2 = reinterpret_cast<const ull*>(Wh) + tcol;

    #pragma unroll 4
    for (int k2 = 0; k2 < KK / 2; ++k2) {
        ull a2[TM], x2[TM], wi2[3], wh2[3];
        #pragma unroll
        for (int r = 0; r < TM; ++r) {
            a2[r] = As2[r * (KK / 2) + k2];
            x2[r] = Xs2[r * (KK / 2) + k2];
        }
        #pragma unroll
        for (int c = 0; c < 3; ++c) {
            wi2[c] = Wi2[k2 * NT + c * TCOLS];
            wh2[c] = Wh2[k2 * NT + c * TCOLS];
        }
        #pragma unroll
        for (int r = 0; r < TM; ++r)
            #pragma unroll
            for (int c = 0; c < 3; ++c) {
                ffma2(gi[r][c], a2[r], wi2[c]);
                ffma2(gh[r][c], x2[r], wh2[c]);
            }
    }

    const float bir = bih[tcol],      bhr = bhh[tcol];
    const float biz = bih[tcol + 64], bhz = bhh[tcol + 64];
    const float bin = bih[tcol + 128], bhn = bhh[tcol + 128];
    #pragma unroll
    for (int r = 0; r < TM; ++r) {
        const int m = m0 + trow * TM + r;
        if (m < M) {
            const float ir = unpack_sum(gi[r][0]) + bir;
            const float hr = unpack_sum(gh[r][0]) + bhr;
            const float iz = unpack_sum(gi[r][1]) + biz;
            const float hz = unpack_sum(gh[r][1]) + bhz;
            const float in_ = unpack_sum(gi[r][2]) + bin;
            const float hn = unpack_sum(gh[r][2]) + bhn;
            const float rg = 1.f / (1.f + __expf(-(ir + hr)));
            const float zg = 1.f / (1.f + __expf(-(iz + hz)));
            const float nv = tanhf(fmaf(rg, hn, in_));
            const float xv = Xs[(trow * TM + r) * KK + tcol];
            out[(size_t)m * 64 + tcol] = (1.f - zg) * nv + zg * xv;
        }
    }
}

// ---------------- launch ----------------
extern "C" void kernel_launch(void* const* d_in, const int* in_sizes, int n_in,
                              void* d_out, int out_size) {
    const float* x   = (const float*)d_in[0];
    const int*   ei  = (const int*)d_in[1];
    const float* ea  = (const float*)d_in[2];
    const float* W1  = (const float*)d_in[3];
    const float* b1  = (const float*)d_in[4];
    const float* W2  = (const float*)d_in[5];
    const float* b2  = (const float*)d_in[6];
    const float* Wih = (const float*)d_in[7];
    const float* bih = (const float*)d_in[8];
    const float* Whh = (const float*)d_in[9];
    const float* bhh = (const float*)d_in[10];
    float* out = (float*)d_out;

    const int M = in_sizes[0] / NDIM;  // 100000
    const int E = in_sizes[1] / 2;     // 1600000

    void *pHagg, *pdeg, *paggr, *pW2t;
    cudaGetSymbolAddress(&pHagg, g_Hagg);
    cudaGetSymbolAddress(&pdeg,  g_degf);
    cudaGetSymbolAddress(&paggr, g_aggr);
    cudaGetSymbolAddress(&pW2t,  g_W2t);

    constexpr int SM1 = (32 * 64 + 64 * 256) * 4;          // 73728
    constexpr int SM2 = (64 * 128 + 128 * 64) * 4;         // 65536
    constexpr int SMG = (2 * 16 * 64 + 2 * 64 * 192) * 4;  // 106496
    cudaFuncSetAttribute(gemm1_kernel, cudaFuncAttributeMaxDynamicSharedMemorySize, SM1);
    cudaFuncSetAttribute(gemm_k<64, 64, 128, 8, 2, 1>,
                         cudaFuncAttributeMaxDynamicSharedMemorySize, SM2);
    cudaFuncSetAttribute(gru_kernel, cudaFuncAttributeMaxDynamicSharedMemorySize, SMG);

    prep_kernel<<<64, 256>>>(W1, b1, W2, Wih, Whh);
    zero_cnt_kernel<<<(NN + 255) / 256, 256>>>();
    hist_kernel<<<(E + 255) / 256, 256>>>(ei, E);

    // A(fp16)/B(fp32): A = x@W1a^T + b1 (gather target), B = x@W1b^T
    gemm1_kernel<<<(M + 31) / 32, 256, SM1>>>(x, M);

    scan1_kernel<<<NB_SCAN, 1024>>>();
    scan2_kernel<<<1, 32>>>();
    scan3_kernel<<<(NN + 1023) / 1024, 1024>>>();
    scatter_kernel<<<(E + 255) / 256, 256>>>(ei, ea, E);

    // per-dst aggregation (no atomics; fp16 gather halves L2 traffic)
    agg_kernel<<<(NN + 7) / 8, 256>>>();

    // aggr[N,64] = Hagg @ W2t + deg * b2
    gemm_k<64, 64, 128, 8, 2, 1><<<(M + 63) / 64, 256, SM2>>>(
        (const float*)pHagg, (const float*)pW2t, b2, (const float*)pdeg, (float*)paggr, M);

    // fused: gi = aggr@Wih^T+bih, gh = x@Whh^T+bhh, GRU gates, write out
    gru_kernel<<<(M + 15) / 16, 256, SMG>>>(
        (const float*)paggr, x, bih, bhh, out, M);
}